// round 15
// baseline (speedup 1.0000x reference)
#include <cuda_runtime.h>
#include <cuda_fp16.h>
#include <cstdint>

#define DIMN 896
#define NKEYS 585

// ==================== device scratch (no allocation) ========================
__device__ float  g_Q  [512   * 896];
__device__ __half g_Ks [512   * 896];
__device__ __half g_Vs [512   * 896];
__device__ __half g_Ka [4160  * 896];
__device__ __half g_Va [4160  * 896];
__device__ __half g_Kt [32768 * 896];
__device__ float  g_y  [512   * 896];
__device__ float2 g_rope[512 * 112];
__device__ __half g_W  [9][896 * 896];   // W^T fp16 [n][k]
__device__ __half g_xh  [512   * 896];
__device__ __half g_hadh[4224  * 896];
__device__ __half g_hth [32768 * 896];
__device__ __half g_ath [512   * 896];
__device__ __half g_ynh [512   * 896];
// attention factorization buffers
__device__ __half g_wt   [64 * 64 * 512];
__device__ float  g_st   [4096];
__device__ float  g_oPart[4096 * 112];
__device__ __half g_wsum [4096 * 896];

// ==================== helpers ===============================================
__device__ __forceinline__ uint32_t smem_u32(const void* p) {
    uint32_t a;
    asm("{ .reg .u64 t; cvta.to.shared.u64 t, %1; cvt.u32.u64 %0, t; }" : "=r"(a) : "l"(p));
    return a;
}
#define CP_ASYNC16(dst, src) asm volatile("cp.async.cg.shared.global [%0], [%1], 16;" :: "r"(dst), "l"(src))
#define CP_COMMIT()          asm volatile("cp.async.commit_group;" ::: "memory")
#define CP_WAIT0()           asm volatile("cp.async.wait_group 0;" ::: "memory")
#define CP_WAIT1()           asm volatile("cp.async.wait_group 1;" ::: "memory")

#define LDSM4(r0, r1, r2, r3, addr) \
    asm volatile("ldmatrix.sync.aligned.m8n8.x4.shared.b16 {%0,%1,%2,%3}, [%4];" \
        : "=r"(r0), "=r"(r1), "=r"(r2), "=r"(r3) : "r"(addr))

#define LDSM4_T(r0, r1, r2, r3, addr) \
    asm volatile("ldmatrix.sync.aligned.m8n8.x4.trans.shared.b16 {%0,%1,%2,%3}, [%4];" \
        : "=r"(r0), "=r"(r1), "=r"(r2), "=r"(r3) : "r"(addr))

#define MMA_F16(d, a, b0, b1) \
    asm volatile("mma.sync.aligned.m16n8k16.row.col.f32.f16.f16.f32 " \
        "{%0,%1,%2,%3}, {%4,%5,%6,%7}, {%8,%9}, {%0,%1,%2,%3};" \
        : "+f"((d)[0]), "+f"((d)[1]), "+f"((d)[2]), "+f"((d)[3]) \
        : "r"((a)[0]), "r"((a)[1]), "r"((a)[2]), "r"((a)[3]), "r"(b0), "r"(b1))

__device__ __forceinline__ uint2 cvt4h(float4 v) {
    __half2 lo = __floats2half2_rn(v.x, v.y);
    __half2 hi = __floats2half2_rn(v.z, v.w);
    return make_uint2(*(uint32_t*)&lo, *(uint32_t*)&hi);
}

// ==================== prep kernels ==========================================
__global__ void cvt_k(const float* __restrict__ src, __half* __restrict__ dst, int n4)
{
    int i = blockIdx.x * blockDim.x + threadIdx.x;
    if (i >= n4) return;
    ((uint2*)dst)[i] = cvt4h(((const float4*)src)[i]);
}

// fused small prep: convw (7056) | build_had (3696) | cvt x (448) | rope (224)
#define SEG_CW   7056
#define SEG_HAD  (SEG_CW + 3696)
#define SEG_X    (SEG_HAD + 448)
#define SEG_ROPE (SEG_X + 224)

struct PrepArgs {
    const float* w[9];
    const float *x, *h_a, *p;
};

__global__ __launch_bounds__(256) void prep2_k(PrepArgs pa)
{
    const int id = blockIdx.x, tid = threadIdx.x;
    __shared__ float tile[32][33];

    if (id < SEG_CW) {                         // weight transpose + fp16
        int b = id;
        int wi = b / 784, rem = b % 784;
        int n0 = (rem % 28) * 32, k0 = (rem / 28) * 32;
        const float* W = pa.w[wi];
        __half* dst = g_W[wi];
        int tx = tid & 31, ty = tid >> 5;
        #pragma unroll
        for (int i = 0; i < 4; i++)
            tile[ty + i * 8][tx] = W[(size_t)(k0 + ty + i * 8) * 896 + n0 + tx];
        __syncthreads();
        #pragma unroll
        for (int i = 0; i < 4; i++)
            dst[(size_t)(n0 + ty + i * 8) * 896 + k0 + tx] = __float2half_rn(tile[tx][ty + i * 8]);
    } else if (id < SEG_HAD) {                 // build h_ad -> fp16 (4224 rows, zero-pad)
        int i = (id - SEG_CW) * 256 + tid;
        int row = i / 224, c4 = i % 224;
        float4 v = make_float4(0.f, 0.f, 0.f, 0.f);
        if (row < 4160) {
            int b = row / 65, l = row % 65;
            v = (l < 64) ? ((const float4*)(pa.h_a + ((size_t)(b * 64 + l)) * 896))[c4]
                         : ((const float4*)(pa.p   + (size_t)b * 896))[c4];
        }
        ((uint2*)g_hadh)[i] = cvt4h(v);
    } else if (id < SEG_X) {                   // cvt x -> fp16
        int i = (id - SEG_HAD) * 256 + tid;
        ((uint2*)g_xh)[i] = cvt4h(((const float4*)pa.x)[i]);
    } else {                                   // rope table
        int i = (id - SEG_X) * 256 + tid;
        int pos = i / 112, d = i % 112, f = d % 56;
        float inv = powf(10000.0f, -((float)(2 * f) / 112.0f));
        float ang = (float)pos * inv;
        g_rope[i] = make_float2(cosf(ang), sinf(ang));
    }
}

// ==================== batched single-pass fp16 GEMM (128x128, KB=32) ========
#define LDAB 80
#define STAGE_B 20480
#define SM_TOTAL (3 * STAGE_B)

struct GB {
    const __half *Ah, *B;
    int M, ncol;
    void* out[3];
    const float* bias[3];
    int epi[3];      // 0 bias; 1 bias+RoPE; 2 bias+res; 3 bias+ReLU
    int rl[3];
    int hout[3];
    const float* res;
};
struct GB3 { GB g[3]; int b0, b1; };

__device__ __forceinline__ void stage_load(
    uint32_t s0, const __half* __restrict__ Ah, const __half* __restrict__ B,
    int row0, int col0, int kt, int tid)
{
    #pragma unroll
    for (int i = 0; i < 4; i++) {
        const int sel = i >> 1;
        int cc = (i & 1) * 256 + tid;
        int r = cc >> 2, ks = cc & 3;
        const __half* base = sel ? B : Ah;
        int rowg = sel ? (col0 + r) : (row0 + r);
        uint32_t dst = s0 + (uint32_t)sel * 10240u + (uint32_t)(r * LDAB + ks * 16);
        CP_ASYNC16(dst, base + (size_t)rowg * 896 + kt + ks * 8);
    }
}

__global__ __launch_bounds__(256, 2) void wgemm_k(GB3 gb)
{
    extern __shared__ __align__(128) char smx[];
    const int id = blockIdx.x;
    const int gi = (id < gb.b0) ? 0 : (id < gb.b1) ? 1 : 2;
    const int local = id - ((gi == 0) ? 0 : (gi == 1) ? gb.b0 : gb.b1);
    const GB& G = gb.g[gi];
    const int colTile = local % G.ncol;
    const int row0 = (local / G.ncol) * 128;
    const int col0 = colTile * 128;

    const int tid  = threadIdx.x;
    const int lane = tid & 31, wid = tid >> 5;
    const int wm = (wid & 3) * 32, wn = (wid >> 2) * 64;
    uint32_t sb = smem_u32(smx);

    float acc[2][8][4];
    #pragma unroll
    for (int mi = 0; mi < 2; mi++)
        #pragma unroll
        for (int nj = 0; nj < 8; nj++)
            #pragma unroll
            for (int q = 0; q < 4; q++) acc[mi][nj][q] = 0.0f;

    const int a_r = lane & 15;
    const int a_k = (lane >> 4) * 16;
    const int b_r = (lane & 7) + ((lane >> 4) & 1) * 8;
    const int b_k = ((lane >> 3) & 1) * 16;

    stage_load(sb, G.Ah, G.B, row0, col0, 0, tid);
    CP_COMMIT();
    stage_load(sb + STAGE_B, G.Ah, G.B, row0, col0, 32, tid);
    CP_COMMIT();

    #pragma unroll 1
    for (int t = 0; t < 28; t++) {
        CP_WAIT1();
        __syncthreads();
        if (t + 2 < 28)
            stage_load(sb + ((t + 2) % 3) * STAGE_B, G.Ah, G.B, row0, col0, (t + 2) * 32, tid);
        CP_COMMIT();

        uint32_t s0 = sb + (t % 3) * STAGE_B;
        uint32_t aB = s0 +         (uint32_t)((wm + a_r) * LDAB + a_k);
        uint32_t bB = s0 + 10240 + (uint32_t)((wn + b_r) * LDAB + b_k);
        #pragma unroll
        for (int ks = 0; ks < 2; ks++) {
            const uint32_t ksb = ks * 32;
            uint32_t a[2][4], bh[8][2];
            #pragma unroll
            for (int mi = 0; mi < 2; mi++)
                LDSM4(a[mi][0], a[mi][1], a[mi][2], a[mi][3], aB + mi * (16 * LDAB) + ksb);
            #pragma unroll
            for (int p = 0; p < 4; p++)
                LDSM4(bh[2*p][0], bh[2*p][1], bh[2*p+1][0], bh[2*p+1][1], bB + p * (16 * LDAB) + ksb);
            #pragma unroll
            for (int mi = 0; mi < 2; mi++)
                #pragma unroll
                for (int nj = 0; nj < 8; nj++)
                    MMA_F16(acc[mi][nj], a[mi], bh[nj][0], bh[nj][1]);
        }
    }

    const int cb = colTile / 7;
    const int lcol0 = (colTile % 7) * 128;
    const float* bias = G.bias[cb];
    const int epi = G.epi[cb];
    const int ropeL = G.rl[cb];
    const int hout = G.hout[cb];

    #pragma unroll
    for (int mi = 0; mi < 2; mi++) {
        #pragma unroll
        for (int half = 0; half < 2; half++) {
            int row = row0 + wm + mi * 16 + (lane >> 2) + half * 8;
            if (row >= G.M) continue;
            const float2* rt = (epi == 1) ? (g_rope + (size_t)(row % ropeL) * 112) : nullptr;
            const float* rrow = (epi == 2) ? (G.res + (size_t)row * DIMN) : nullptr;
            float* crowf = (float*)G.out[cb] + (size_t)row * DIMN;
            __half* crowh = (__half*)G.out[cb] + (size_t)row * DIMN;
            #pragma unroll
            for (int nj = 0; nj < 8; nj++) {
                int gc = lcol0 + wn + nj * 8 + (lane & 3) * 2;
                float v0 = acc[mi][nj][half * 2]     + bias[gc];
                float v1 = acc[mi][nj][half * 2 + 1] + bias[gc + 1];
                float2 o;
                if (epi == 1) {
                    int d = gc % 112;
                    float2 r0 = rt[d], r1 = rt[d + 1];
                    o.x = v0 * r0.x - v1 * r0.y;
                    o.y = v1 * r1.x + v0 * r1.y;
                } else if (epi == 2) {
                    o.x = v0 + rrow[gc]; o.y = v1 + rrow[gc + 1];
                } else if (epi == 3) {
                    o.x = fmaxf(v0, 0.f); o.y = fmaxf(v1, 0.f);
                } else {
                    o.x = v0; o.y = v1;
                }
                if (hout) {
                    __half2 h2 = __floats2half2_rn(o.x, o.y);
                    *(uint32_t*)(crowh + gc) = *(uint32_t*)&h2;
                } else {
                    *(float2*)(crowf + gc) = o;
                }
            }
        }
    }
}

// ==================== tail GEMM: 128x128 tile, KB=128, 2-stage, occ 1 =======
#define TLDAB  272
#define TSTAGE 69632
#define TSM    (2 * TSTAGE)

struct TGp {
    const __half *A, *B;
    int mode;
    void* out;
    const float *bias, *res;
};

__global__ __launch_bounds__(256, 1) void tailg_k(TGp tg)
{
    extern __shared__ __align__(128) char smx[];
    const int tid = threadIdx.x, lane = tid & 31, wid = tid >> 5;
    const int wm = (wid & 3) * 32, wn = (wid >> 2) * 64;
    uint32_t sb = smem_u32(smx);

    int h = 0, row0, col0;
    if (tg.mode == 2) {
        h = blockIdx.x >> 2;
        row0 = (blockIdx.x & 3) * 128;
        col0 = 0;
    } else {
        row0 = (blockIdx.x / 7) * 128;
        col0 = (blockIdx.x % 7) * 128;
    }
    const int brow0 = (tg.mode == 2) ? (h * 112) : col0;

    float acc[2][8][4];
    #pragma unroll
    for (int mi = 0; mi < 2; mi++)
        #pragma unroll
        for (int nj = 0; nj < 8; nj++)
            #pragma unroll
            for (int q = 0; q < 4; q++) acc[mi][nj][q] = 0.0f;

    const int a_r = lane & 15;
    const int a_k = (lane >> 4) * 16;
    const int b_r = (lane & 7) + ((lane >> 4) & 1) * 8;
    const int b_k = ((lane >> 3) & 1) * 16;

    auto loadst = [&](uint32_t s0, int kt) {
        #pragma unroll
        for (int i = 0; i < 16; i++) {
            const int sel = i >> 3;
            int cc = (i & 7) * 256 + tid;
            int r = cc >> 4, ks = cc & 15;
            uint32_t dst = s0 + (uint32_t)sel * 34816u + (uint32_t)(r * TLDAB + ks * 16);
            if (sel == 0) {
                int rr = row0 + r;
                int grow = (tg.mode == 2) ? (((rr >> 3) << 6) + h * 8 + (rr & 7)) : rr;
                CP_ASYNC16(dst, tg.A + (size_t)grow * 896 + kt + ks * 8);
            } else {
                int brow = brow0 + r;
                if (brow > 895) brow = 895;
                CP_ASYNC16(dst, tg.B + (size_t)brow * 896 + kt + ks * 8);
            }
        }
        CP_COMMIT();
    };

    loadst(sb, 0);

    #pragma unroll 1
    for (int t = 0; t < 7; t++) {
        CP_WAIT0();
        __syncthreads();
        if (t + 1 < 7)
            loadst(sb + ((t + 1) & 1) * TSTAGE, (t + 1) * 128);

        uint32_t s0 = sb + (t & 1) * TSTAGE;
        uint32_t aB = s0 +          (uint32_t)((wm + a_r) * TLDAB + a_k);
        uint32_t bB = s0 + 34816u + (uint32_t)((wn + b_r) * TLDAB + b_k);
        #pragma unroll
        for (int ks = 0; ks < 8; ks++) {
            const uint32_t ksb = ks * 32;
            uint32_t a[2][4], bh[8][2];
            #pragma unroll
            for (int mi = 0; mi < 2; mi++)
                LDSM4(a[mi][0], a[mi][1], a[mi][2], a[mi][3], aB + mi * (16 * TLDAB) + ksb);
            #pragma unroll
            for (int p = 0; p < 4; p++)
                LDSM4(bh[2*p][0], bh[2*p][1], bh[2*p+1][0], bh[2*p+1][1], bB + p * (16 * TLDAB) + ksb);
            #pragma unroll
            for (int mi = 0; mi < 2; mi++)
                #pragma unroll
                for (int nj = 0; nj < 8; nj++)
                    MMA_F16(acc[mi][nj], a[mi], bh[nj][0], bh[nj][1]);
        }
        __syncthreads();
    }

    // ---------------- epilogue ----------------
    #pragma unroll
    for (int mi = 0; mi < 2; mi++) {
        #pragma unroll
        for (int half = 0; half < 2; half++) {
            int row = row0 + wm + mi * 16 + (lane >> 2) + half * 8;
            if (tg.mode == 2) {
                int bq = row >> 3, tq = row & 7;
                float stv = g_st[(bq * 8 + h) * 8 + tq];
                const float* op = g_oPart + ((size_t)(bq * 8 + h) * 8 + tq) * 112;
                __half* crow = g_ath + ((size_t)(bq * 8 + tq)) * 896 + h * 112;
                #pragma unroll
                for (int nj = 0; nj < 8; nj++) {
                    int gc = wn + nj * 8 + (lane & 3) * 2;
                    if (gc >= 112) continue;
                    float v0 = acc[mi][nj][half * 2]     + op[gc]     + stv * tg.bias[h * 112 + gc];
                    float v1 = acc[mi][nj][half * 2 + 1] + op[gc + 1] + stv * tg.bias[h * 112 + gc + 1];
                    __half2 h2 = __floats2half2_rn(v0, v1);
                    *(uint32_t*)(crow + gc) = *(uint32_t*)&h2;
                }
            } else {
                float* crow = (float*)tg.out + (size_t)row * DIMN;
                const float* rrow = (tg.mode == 0) ? (tg.res + (size_t)row * DIMN) : nullptr;
                #pragma unroll
                for (int nj = 0; nj < 8; nj++) {
                    int gc = col0 + wn + nj * 8 + (lane & 3) * 2;
                    float v0 = acc[mi][nj][half * 2]     + tg.bias[gc];
                    float v1 = acc[mi][nj][half * 2 + 1] + tg.bias[gc + 1];
                    float2 o;
                    if (tg.mode == 0) { o.x = v0 + rrow[gc]; o.y = v1 + rrow[gc + 1]; }
                    else              { o.x = fmaxf(v0, 0.f); o.y = fmaxf(v1, 0.f); }
                    *(float2*)(crow + gc) = o;
                }
            }
        }
    }
}

// ==================== attention (scores + softmax + self/ad AV) =============
__global__ __launch_bounds__(256) void attn_k(const float* __restrict__ gate)
{
    const int b = blockIdx.x >> 3, h = blockIdx.x & 7;
    __shared__ float q_s[8][112];
    __shared__ float w_s[8][592];
    __shared__ const __half* kp[NKEYS];
    __shared__ const __half* vp[73];
    const int tid = threadIdx.x;

    for (int i = tid; i < 8 * 112; i += 256) {
        int r = i / 112, d = i % 112;
        q_s[r][d] = g_Q[((size_t)(b * 8 + r)) * 896 + h * 112 + d];
    }
    for (int k = tid; k < NKEYS; k += 256) {
        size_t o;
        if (k < 8)       { o = ((size_t)(b * 8 + k)) * 896 + h * 112;          kp[k] = g_Ks + o; vp[k] = g_Vs + o; }
        else if (k < 73) { o = ((size_t)(b * 65 + (k - 8))) * 896 + h * 112;   kp[k] = g_Ka + o; vp[k] = g_Va + o; }
        else             { o = ((size_t)(b * 512 + (k - 73))) * 896 + h * 112; kp[k] = g_Kt + o; }
    }
    __syncthreads();

    const float ratio = tanhf(gate[0]);
    const float sc0   = rsqrtf(112.0f);

    for (int k = tid; k < NKEYS; k += 256) {
        const __half* kb = kp[k];
        float acc[8] = {0.f, 0.f, 0.f, 0.f, 0.f, 0.f, 0.f, 0.f};
        #pragma unroll 2
        for (int d8 = 0; d8 < 14; ++d8) {
            uint4 raw = *(const uint4*)(kb + d8 * 8);
            const __half2* hp = (const __half2*)&raw;
            float2 f0 = __half22float2(hp[0]);
            float2 f1 = __half22float2(hp[1]);
            float2 f2 = __half22float2(hp[2]);
            float2 f3 = __half22float2(hp[3]);
            #pragma unroll
            for (int r = 0; r < 8; r++) {
                const float* q = &q_s[r][d8 * 8];
                acc[r] = fmaf(q[0], f0.x, acc[r]);
                acc[r] = fmaf(q[1], f0.y, acc[r]);
                acc[r] = fmaf(q[2], f1.x, acc[r]);
                acc[r] = fmaf(q[3], f1.y, acc[r]);
                acc[r] = fmaf(q[4], f2.x, acc[r]);
                acc[r] = fmaf(q[5], f2.y, acc[r]);
                acc[r] = fmaf(q[6], f3.x, acc[r]);
                acc[r] = fmaf(q[7], f3.y, acc[r]);
            }
        }
        float sc = (k < 73) ? sc0 : sc0 * ratio;
        #pragma unroll
        for (int r = 0; r < 8; r++) w_s[r][k] = acc[r] * sc;
    }
    __syncthreads();

    {
        int r = tid >> 5, lane = tid & 31;
        float m = -3.0e38f;
        for (int k = lane; k < NKEYS; k += 32) m = fmaxf(m, w_s[r][k]);
        #pragma unroll
        for (int o = 16; o; o >>= 1) m = fmaxf(m, __shfl_xor_sync(0xffffffffu, m, o));
        float s = 0.0f;
        for (int k = lane; k < NKEYS; k += 32) { float e = __expf(w_s[r][k] - m); w_s[r][k] = e; s += e; }
        #pragma unroll
        for (int o = 16; o; o >>= 1) s += __shfl_xor_sync(0xffffffffu, s, o);
        float inv = 1.0f / s;
        for (int k = lane; k < NKEYS; k += 32) w_s[r][k] *= inv;
        float sv = 0.0f;
        for (int k = 73 + lane; k < NKEYS; k += 32) sv += w_s[r][k];
        #pragma unroll
        for (int o = 16; o; o >>= 1) sv += __shfl_xor_sync(0xffffffffu, sv, o);
        if (lane == 0) g_st[(b * 8 + h) * 8 + r] = sv;
    }
    __syncthreads();

    for (int i = tid; i < 8 * 512; i += 256) {
        int t = i >> 9, k = i & 511;
        g_wt[((size_t)b * 64 + h * 8 + t) * 512 + k] = __float2half_rn(w_s[t][73 + k]);
    }

    for (int idx = tid; idx < 896; idx += 256) {
        int r = idx / 112, d = idx % 112;
        float acc = 0.0f;
        #pragma unroll 4
        for (int k = 0; k < 73; k++) acc = fmaf(w_s[r][k], __half2float(vp[k][d]), acc);
        g_oPart[((size_t)(b * 8 + h) * 8 + r) * 112 + d] = acc;
    }
}

// ==================== wsum GEMM: w_t[b](64x512) @ h_t[b](512x896), KB=64 ====
#define WS_LDA 72
#define WS_LDB 136
__global__ __launch_bounds__(256, 2) void wsum_k()
{
    __shared__ __half sA[2][64 * WS_LDA];
    __shared__ __half sB[2][64 * WS_LDB];
    const int bb = blockIdx.x / 7;
    const int col0 = (blockIdx.x % 7) * 128;
    const int tid = threadIdx.x, lane = tid & 31, wid = tid >> 5;
    const int wmi = wid >> 2, wni = wid & 3;

    const __half* Aw = g_wt  + (size_t)bb * 64 * 512;
    const __half* Bh = g_hth + (size_t)bb * 512 * 896 + col0;

    float acc[2][4][4];
    #pragma unroll
    for (int mi = 0; mi < 2; mi++)
        #pragma unroll
        for (int nj = 0; nj < 4; nj++)
            #pragma unroll
            for (int q = 0; q < 4; q++) acc[mi][nj][q] = 0.0f;

    const int bt_k = (lane % 8) + (lane & 8);
    const int bt_n = (lane & 16) >> 1;

    auto loadst = [&](int st, int kt) {
        #pragma unroll
        for (int i = 0; i < 2; i++) {
            int idx = i * 256 + tid;
            int r = idx >> 3, c = idx & 7;
            CP_ASYNC16(smem_u32(&sA[st][r * WS_LDA + c * 8]), Aw + (size_t)r * 512 + kt + c * 8);
        }
        #pragma unroll
        for (int i = 0; i < 4; i++) {
            int idx = i * 256 + tid;
            int rr = idx >> 4, cx = idx & 15;
            CP_ASYNC16(smem_u32(&sB[st][rr * WS_LDB + cx * 8]), Bh + (size_t)(kt + rr) * 896 + cx * 8);
        }
        CP_COMMIT();
    };

    loadst(0, 0);

    #pragma unroll 1
    for (int t = 0; t < 8; t++) {
        CP_WAIT0();
        __syncthreads();
        if (t + 1 < 8)
            loadst((t + 1) & 1, (t + 1) * 64);
        const int buf = t & 1;
        #pragma unroll
        for (int ks = 0; ks < 4; ks++) {
            uint32_t a[2][4], bf[4][2];
            #pragma unroll
            for (int mi = 0; mi < 2; mi++) {
                uint32_t aaddr = smem_u32(&sA[buf][(wmi * 32 + mi * 16 + (lane & 15)) * WS_LDA])
                                 + ((lane >> 4) * 16) + ks * 32;
                LDSM4(a[mi][0], a[mi][1], a[mi][2], a[mi][3], aaddr);
            }
            #pragma unroll
            for (int nb = 0; nb < 2; nb++) {
                uint32_t baddr = smem_u32(&sB[buf][(ks * 16 + bt_k) * WS_LDB
                                  + wni * 32 + nb * 16 + bt_n]);
                LDSM4_T(bf[2*nb][0], bf[2*nb][1], bf[2*nb+1][0], bf[2*nb+1][1], baddr);
            }
            #pragma unroll
            for (int mi = 0; mi < 2; mi++)
                #pragma unroll
                for (int nj = 0; nj < 4; nj++)
                    MMA_F16(acc[mi][nj], a[mi], bf[nj][0], bf[nj][1]);
        }
        __syncthreads();
    }

    #pragma unroll
    for (int mi = 0; mi < 2; mi++) {
        #pragma unroll
        for (int half = 0; half < 2; half++) {
            int r = wmi * 32 + mi * 16 + (lane >> 2) + half * 8;
            __half* crow = g_wsum + ((size_t)bb * 64 + r) * 896;
            #pragma unroll
            for (int nj = 0; nj < 4; nj++) {
                int gc = col0 + wni * 32 + nj * 8 + (lane & 3) * 2;
                __half2 h2 = __floats2half2_rn(acc[mi][nj][half * 2], acc[mi][nj][half * 2 + 1]);
                *(uint32_t*)(crow + gc) = *(uint32_t*)&h2;
            }
        }
    }
}

// ==================== layernorm (emits fp16) ================================
__global__ __launch_bounds__(256) void ln_k(const float* __restrict__ g,
                                            const float* __restrict__ bt)
{
    int row = blockIdx.x;
    const float* y = g_y + (size_t)row * 896;
    int tid = threadIdx.x;
    float s = 0.0f, s2 = 0.0f;
    for (int j = tid; j < 896; j += 256) { float v = y[j]; s += v; s2 += v * v; }
    __shared__ float rs[8], rs2[8];
    #pragma unroll
    for (int o = 16; o; o >>= 1) { s += __shfl_xor_sync(~0u, s, o); s2 += __shfl_xor_sync(~0u, s2, o); }
    if ((tid & 31) == 0) { rs[tid >> 5] = s; rs2[tid >> 5] = s2; }
    __syncthreads();
    if (tid < 32) {
        s  = (tid < 8) ? rs[tid]  : 0.0f;
        s2 = (tid < 8) ? rs2[tid] : 0.0f;
        #pragma unroll
        for (int o = 4; o; o >>= 1) { s += __shfl_xor_sync(~0u, s, o); s2 += __shfl_xor_sync(~0u, s2, o); }
        if (tid == 0) { rs[0] = s; rs2[0] = s2; }
    }
    __syncthreads();
    float mu  = rs[0]  * (1.0f / 896.0f);
    float var = rs2[0] * (1.0f / 896.0f) - mu * mu;
    float inv = rsqrtf(var + 1e-5f);
    for (int j = tid; j < 896; j += 256)
        g_ynh[(size_t)row * 896 + j] = __float2half_rn((y[j] - mu) * inv * g[j] + bt[j]);
}

// ==================== host orchestration ====================================
extern "C" void kernel_launch(void* const* d_in, const int* in_sizes, int n_in,
                              void* d_out, int out_size)
{
    const float* x   = (const float*)d_in[0];
    const float* h_a = (const float*)d_in[1];
    const float* h_t = (const float*)d_in[2];
    const float* p   = (const float*)d_in[3];
    const float* Wq  = (const float*)d_in[4],  *bq  = (const float*)d_in[5];
    const float* Wks = (const float*)d_in[6],  *bks = (const float*)d_in[7];
    const float* Wvs = (const float*)d_in[8],  *bvs = (const float*)d_in[9];
    const float* Wka = (const float*)d_in[10], *bka = (const float*)d_in[11];
    const float* Wva = (const float*)d_in[12], *bva = (const float*)d_in[13];
    const float* Wkt = (const float*)d_in[14], *bkt = (const float*)d_in[15];
    const float* Wvt = (const float*)d_in[16], *bvt = (const float*)d_in[17];
    const float* Wo  = (const float*)d_in[18], *bo  = (const float*)d_in[19];
    const float* Wf  = (const float*)d_in[20], *bf  = (const float*)d_in[21];
    const float* gate = (const float*)d_in[22];
    const float* ln_g = (const float*)d_in[23];
    const float* ln_b = (const float*)d_in[24];

    float *Q, *y;
    __half *Ks, *Vs, *Ka, *Va, *Kt;
    __half *W, *xh, *hadh, *hth, *ath, *ynh, *wsum;
    cudaGetSymbolAddress((void**)&Q,    g_Q);
    cudaGetSymbolAddress((void**)&Ks,   g_Ks);
    cudaGetSymbolAddress((void**)&Vs,   g_Vs);
    cudaGetSymbolAddress((void**)&Ka,   g_Ka);
    cudaGetSymbolAddress((void**)&Va,   g_Va);
    cudaGetSymbolAddress((void**)&Kt,   g_Kt);
    cudaGetSymbolAddress((void**)&y,    g_y);
    cudaGetSymbolAddress((void**)&W,    g_W);
    cudaGetSymbolAddress((void**)&xh,   g_xh);
    cudaGetSymbolAddress((void**)&hadh, g_hadh);
    cudaGetSymbolAddress((void**)&hth,  g_hth);
    cudaGetSymbolAddress((void**)&ath,  g_ath);
    cudaGetSymbolAddress((void**)&ynh,  g_ynh);
    cudaGetSymbolAddress((void**)&wsum, g_wsum);

    cudaFuncSetAttribute(wgemm_k, cudaFuncAttributeMaxDynamicSharedMemorySize, SM_TOTAL);
    cudaFuncSetAttribute(tailg_k, cudaFuncAttributeMaxDynamicSharedMemorySize, TSM);

    // big streaming convert first (long pole), then fused small prep
    cvt_k<<<(32768 * 224 + 255) / 256, 256>>>(h_t, hth, 32768 * 224);

    {
        PrepArgs pa;
        pa.w[0] = Wq; pa.w[1] = Wks; pa.w[2] = Wvs; pa.w[3] = Wka; pa.w[4] = Wva;
        pa.w[5] = Wkt; pa.w[6] = Wvt; pa.w[7] = Wo; pa.w[8] = Wf;
        pa.x = x; pa.h_a = h_a; pa.p = p;
        prep2_k<<<SEG_ROPE, 256>>>(pa);
    }

    const size_t WS = 896 * 896;

    // ---- batched GEMM: Kt (1792) + Ka/Va (462) + QKV (84) ------------------
    {
        GB3 gb;
        gb.g[0].Ah = hth; gb.g[0].B = W + 5 * WS;
        gb.g[0].M = 32768; gb.g[0].ncol = 7;
        gb.g[0].out[0] = Kt; gb.g[0].bias[0] = bkt; gb.g[0].epi[0] = 1; gb.g[0].rl[0] = 512; gb.g[0].hout[0] = 1;
        gb.g[0].out[1] = nullptr; gb.g[0].bias[1] = nullptr; gb.g[0].epi[1] = 0; gb.g[0].rl[1] = 1; gb.g[0].hout[1] = 0;
        gb.g[0].out[2] = nullptr; gb.g[0].bias[2] = nullptr; gb.g[0].epi[2] = 0; gb.g[0].rl[2] = 1; gb.g[0].hout[2] = 0;
        gb.g[0].res = nullptr;

        gb.g[1].Ah = hadh; gb.g[1].B = W + 3 * WS;
        gb.g[1].M = 4160; gb.g[1].ncol = 14;
        gb.g[1].out[0] = Ka; gb.g[1].bias[0] = bka; gb.g[1].epi[0] = 1; gb.g[1].rl[0] = 65; gb.g[1].hout[0] = 1;
        gb.g[1].out[1] = Va; gb.g[1].bias[1] = bva; gb.g[1].epi[1] = 0; gb.g[1].rl[1] = 1;  gb.g[1].hout[1] = 1;
        gb.g[1].out[2] = nullptr; gb.g[1].bias[2] = nullptr; gb.g[1].epi[2] = 0; gb.g[1].rl[2] = 1; gb.g[1].hout[2] = 0;
        gb.g[1].res = nullptr;

        gb.g[2].Ah = xh; gb.g[2].B = W;
        gb.g[2].M = 512; gb.g[2].ncol = 21;
        gb.g[2].out[0] = Q;  gb.g[2].bias[0] = bq;  gb.g[2].epi[0] = 1; gb.g[2].rl[0] = 8; gb.g[2].hout[0] = 0;
        gb.g[2].out[1] = Ks; gb.g[2].bias[1] = bks; gb.g[2].epi[1] = 1; gb.g[2].rl[1] = 8; gb.g[2].hout[1] = 1;
        gb.g[2].out[2] = Vs; gb.g[2].bias[2] = bvs; gb.g[2].epi[2] = 0; gb.g[2].rl[2] = 1; gb.g[2].hout[2] = 1;
        gb.g[2].res = nullptr;
        gb.b0 = 1792; gb.b1 = 1792 + 462;
        wgemm_k<<<1792 + 462 + 84, 256, SM_TOTAL>>>(gb);
    }

    attn_k<<<512, 256>>>(gate);
    wsum_k<<<64 * 7, 256>>>();

    // ---- proj (mode 2): 32 CTAs, KB=128 -------------------------------------
    {
        TGp tg;
        tg.A = wsum; tg.B = W + 6 * WS; tg.mode = 2;
        tg.out = nullptr; tg.bias = bvt; tg.res = nullptr;
        tailg_k<<<32, 256, TSM>>>(tg);
    }

    // ---- Wo (mode 0): 28 CTAs, KB=128 ---------------------------------------
    {
        TGp tg;
        tg.A = ath; tg.B = W + 7 * WS; tg.mode = 0;
        tg.out = y; tg.bias = bo; tg.res = x;
        tailg_k<<<28, 256, TSM>>>(tg);
    }

    ln_k<<<512, 256>>>(ln_g, ln_b);

    // ---- Wf (mode 1): 28 CTAs, KB=128 ---------------------------------------
    {
        TGp tg;
        tg.A = ynh; tg.B = W + 8 * WS; tg.mode = 1;
        tg.out = d_out; tg.bias = bf; tg.res = nullptr;
        tailg_k<<<28, 256, TSM>>>(tg);
    }
}

// round 16
// speedup vs baseline: 1.0087x; 1.0087x over previous
#include <cuda_runtime.h>
#include <cuda_fp16.h>
#include <cstdint>

#define DIMN 896
#define NKEYS 585

// ==================== device scratch (no allocation) ========================
__device__ float  g_Q  [512   * 896];
__device__ __half g_Ks [512   * 896];
__device__ __half g_Vs [512   * 896];
__device__ __half g_Ka [4160  * 896];
__device__ __half g_Va [4160  * 896];
__device__ __half g_Kt [32768 * 896];
__device__ float  g_y  [512   * 896];
__device__ float2 g_rope[512 * 112];
__device__ __half g_W  [9][896 * 896];   // W^T fp16 [n][k]
__device__ __half g_xh  [512   * 896];
__device__ __half g_hadh[4224  * 896];
__device__ __half g_hth [32768 * 896];
__device__ __half g_ath [512   * 896];
__device__ __half g_ynh [512   * 896];
// attention factorization buffers
__device__ __half g_wt   [64 * 64 * 512];
__device__ float  g_st   [4096];
__device__ float  g_oPart[4096 * 112];
__device__ __half g_wsum [4096 * 896];

// ==================== helpers ===============================================
__device__ __forceinline__ uint32_t smem_u32(const void* p) {
    uint32_t a;
    asm("{ .reg .u64 t; cvta.to.shared.u64 t, %1; cvt.u32.u64 %0, t; }" : "=r"(a) : "l"(p));
    return a;
}
#define CP_ASYNC16(dst, src) asm volatile("cp.async.cg.shared.global [%0], [%1], 16;" :: "r"(dst), "l"(src))
#define CP_COMMIT()          asm volatile("cp.async.commit_group;" ::: "memory")
#define CP_WAIT0()           asm volatile("cp.async.wait_group 0;" ::: "memory")
#define CP_WAIT1()           asm volatile("cp.async.wait_group 1;" ::: "memory")

#define LDSM4(r0, r1, r2, r3, addr) \
    asm volatile("ldmatrix.sync.aligned.m8n8.x4.shared.b16 {%0,%1,%2,%3}, [%4];" \
        : "=r"(r0), "=r"(r1), "=r"(r2), "=r"(r3) : "r"(addr))

#define LDSM4_T(r0, r1, r2, r3, addr) \
    asm volatile("ldmatrix.sync.aligned.m8n8.x4.trans.shared.b16 {%0,%1,%2,%3}, [%4];" \
        : "=r"(r0), "=r"(r1), "=r"(r2), "=r"(r3) : "r"(addr))

#define MMA_F16(d, a, b0, b1) \
    asm volatile("mma.sync.aligned.m16n8k16.row.col.f32.f16.f16.f32 " \
        "{%0,%1,%2,%3}, {%4,%5,%6,%7}, {%8,%9}, {%0,%1,%2,%3};" \
        : "+f"((d)[0]), "+f"((d)[1]), "+f"((d)[2]), "+f"((d)[3]) \
        : "r"((a)[0]), "r"((a)[1]), "r"((a)[2]), "r"((a)[3]), "r"(b0), "r"(b1))

__device__ __forceinline__ uint2 cvt4h(float4 v) {
    __half2 lo = __floats2half2_rn(v.x, v.y);
    __half2 hi = __floats2half2_rn(v.z, v.w);
    return make_uint2(*(uint32_t*)&lo, *(uint32_t*)&hi);
}

// ==================== prep kernels ==========================================
__global__ void cvt_k(const float* __restrict__ src, __half* __restrict__ dst, int n4)
{
    int i = blockIdx.x * blockDim.x + threadIdx.x;
    if (i >= n4) return;
    ((uint2*)dst)[i] = cvt4h(((const float4*)src)[i]);
}

// fused small prep: convw (7056) | build_had (3696) | cvt x (448) | rope (224)
#define SEG_CW   7056
#define SEG_HAD  (SEG_CW + 3696)
#define SEG_X    (SEG_HAD + 448)
#define SEG_ROPE (SEG_X + 224)

struct PrepArgs {
    const float* w[9];
    const float *x, *h_a, *p;
};

__global__ __launch_bounds__(256) void prep2_k(PrepArgs pa)
{
    const int id = blockIdx.x, tid = threadIdx.x;
    __shared__ float tile[32][33];

    if (id < SEG_CW) {
        int b = id;
        int wi = b / 784, rem = b % 784;
        int n0 = (rem % 28) * 32, k0 = (rem / 28) * 32;
        const float* W = pa.w[wi];
        __half* dst = g_W[wi];
        int tx = tid & 31, ty = tid >> 5;
        #pragma unroll
        for (int i = 0; i < 4; i++)
            tile[ty + i * 8][tx] = W[(size_t)(k0 + ty + i * 8) * 896 + n0 + tx];
        __syncthreads();
        #pragma unroll
        for (int i = 0; i < 4; i++)
            dst[(size_t)(n0 + ty + i * 8) * 896 + k0 + tx] = __float2half_rn(tile[tx][ty + i * 8]);
    } else if (id < SEG_HAD) {
        int i = (id - SEG_CW) * 256 + tid;
        int row = i / 224, c4 = i % 224;
        float4 v = make_float4(0.f, 0.f, 0.f, 0.f);
        if (row < 4160) {
            int b = row / 65, l = row % 65;
            v = (l < 64) ? ((const float4*)(pa.h_a + ((size_t)(b * 64 + l)) * 896))[c4]
                         : ((const float4*)(pa.p   + (size_t)b * 896))[c4];
        }
        ((uint2*)g_hadh)[i] = cvt4h(v);
    } else if (id < SEG_X) {
        int i = (id - SEG_HAD) * 256 + tid;
        ((uint2*)g_xh)[i] = cvt4h(((const float4*)pa.x)[i]);
    } else {
        int i = (id - SEG_X) * 256 + tid;
        int pos = i / 112, d = i % 112, f = d % 56;
        float inv = powf(10000.0f, -((float)(2 * f) / 112.0f));
        float ang = (float)pos * inv;
        g_rope[i] = make_float2(cosf(ang), sinf(ang));
    }
}

// ==================== batched single-pass fp16 GEMM (128x128, KB=32) ========
#define LDAB 80
#define STAGE_B 20480
#define SM_TOTAL (3 * STAGE_B)

struct GB {
    const __half *Ah, *B;
    int M, ncol;
    void* out[3];
    const float* bias[3];
    int epi[3];      // 0 bias; 1 bias+RoPE; 2 bias+res; 3 bias+ReLU
    int rl[3];
    int hout[3];
    const float* res;
};
struct GB3 { GB g[3]; int b0, b1; };

__device__ __forceinline__ void stage_load(
    uint32_t s0, const __half* __restrict__ Ah, const __half* __restrict__ B,
    int row0, int col0, int kt, int tid)
{
    #pragma unroll
    for (int i = 0; i < 4; i++) {
        const int sel = i >> 1;
        int cc = (i & 1) * 256 + tid;
        int r = cc >> 2, ks = cc & 3;
        const __half* base = sel ? B : Ah;
        int rowg = sel ? (col0 + r) : (row0 + r);
        uint32_t dst = s0 + (uint32_t)sel * 10240u + (uint32_t)(r * LDAB + ks * 16);
        CP_ASYNC16(dst, base + (size_t)rowg * 896 + kt + ks * 8);
    }
}

__global__ __launch_bounds__(256, 2) void wgemm_k(GB3 gb)
{
    extern __shared__ __align__(128) char smx[];
    const int id = blockIdx.x;
    const int gi = (id < gb.b0) ? 0 : (id < gb.b1) ? 1 : 2;
    const int local = id - ((gi == 0) ? 0 : (gi == 1) ? gb.b0 : gb.b1);
    const GB& G = gb.g[gi];
    const int colTile = local % G.ncol;
    const int row0 = (local / G.ncol) * 128;
    const int col0 = colTile * 128;

    const int tid  = threadIdx.x;
    const int lane = tid & 31, wid = tid >> 5;
    const int wm = (wid & 3) * 32, wn = (wid >> 2) * 64;
    uint32_t sb = smem_u32(smx);

    float acc[2][8][4];
    #pragma unroll
    for (int mi = 0; mi < 2; mi++)
        #pragma unroll
        for (int nj = 0; nj < 8; nj++)
            #pragma unroll
            for (int q = 0; q < 4; q++) acc[mi][nj][q] = 0.0f;

    const int a_r = lane & 15;
    const int a_k = (lane >> 4) * 16;
    const int b_r = (lane & 7) + ((lane >> 4) & 1) * 8;
    const int b_k = ((lane >> 3) & 1) * 16;

    stage_load(sb, G.Ah, G.B, row0, col0, 0, tid);
    CP_COMMIT();
    stage_load(sb + STAGE_B, G.Ah, G.B, row0, col0, 32, tid);
    CP_COMMIT();

    #pragma unroll 1
    for (int t = 0; t < 28; t++) {
        CP_WAIT1();
        __syncthreads();
        if (t + 2 < 28)
            stage_load(sb + ((t + 2) % 3) * STAGE_B, G.Ah, G.B, row0, col0, (t + 2) * 32, tid);
        CP_COMMIT();

        uint32_t s0 = sb + (t % 3) * STAGE_B;
        uint32_t aB = s0 +         (uint32_t)((wm + a_r) * LDAB + a_k);
        uint32_t bB = s0 + 10240 + (uint32_t)((wn + b_r) * LDAB + b_k);
        #pragma unroll
        for (int ks = 0; ks < 2; ks++) {
            const uint32_t ksb = ks * 32;
            uint32_t a[2][4], bh[8][2];
            #pragma unroll
            for (int mi = 0; mi < 2; mi++)
                LDSM4(a[mi][0], a[mi][1], a[mi][2], a[mi][3], aB + mi * (16 * LDAB) + ksb);
            #pragma unroll
            for (int p = 0; p < 4; p++)
                LDSM4(bh[2*p][0], bh[2*p][1], bh[2*p+1][0], bh[2*p+1][1], bB + p * (16 * LDAB) + ksb);
            #pragma unroll
            for (int mi = 0; mi < 2; mi++)
                #pragma unroll
                for (int nj = 0; nj < 8; nj++)
                    MMA_F16(acc[mi][nj], a[mi], bh[nj][0], bh[nj][1]);
        }
    }

    const int cb = colTile / 7;
    const int lcol0 = (colTile % 7) * 128;
    const float* bias = G.bias[cb];
    const int epi = G.epi[cb];
    const int ropeL = G.rl[cb];
    const int hout = G.hout[cb];

    #pragma unroll
    for (int mi = 0; mi < 2; mi++) {
        #pragma unroll
        for (int half = 0; half < 2; half++) {
            int row = row0 + wm + mi * 16 + (lane >> 2) + half * 8;
            if (row >= G.M) continue;
            const float2* rt = (epi == 1) ? (g_rope + (size_t)(row % ropeL) * 112) : nullptr;
            const float* rrow = (epi == 2) ? (G.res + (size_t)row * DIMN) : nullptr;
            float* crowf = (float*)G.out[cb] + (size_t)row * DIMN;
            __half* crowh = (__half*)G.out[cb] + (size_t)row * DIMN;
            #pragma unroll
            for (int nj = 0; nj < 8; nj++) {
                int gc = lcol0 + wn + nj * 8 + (lane & 3) * 2;
                float v0 = acc[mi][nj][half * 2]     + bias[gc];
                float v1 = acc[mi][nj][half * 2 + 1] + bias[gc + 1];
                float2 o;
                if (epi == 1) {
                    int d = gc % 112;
                    float2 r0 = rt[d], r1 = rt[d + 1];
                    o.x = v0 * r0.x - v1 * r0.y;
                    o.y = v1 * r1.x + v0 * r1.y;
                } else if (epi == 2) {
                    o.x = v0 + rrow[gc]; o.y = v1 + rrow[gc + 1];
                } else if (epi == 3) {
                    o.x = fmaxf(v0, 0.f); o.y = fmaxf(v1, 0.f);
                } else {
                    o.x = v0; o.y = v1;
                }
                if (hout) {
                    __half2 h2 = __floats2half2_rn(o.x, o.y);
                    *(uint32_t*)(crowh + gc) = *(uint32_t*)&h2;
                } else {
                    *(float2*)(crowf + gc) = o;
                }
            }
        }
    }
}

// ==================== tail GEMM: 128x128 tile, KB=128, 2-stage, occ 1 =======
#define TLDAB  272
#define TSTAGE 69632
#define TSM    (2 * TSTAGE)

struct TGp {
    const __half *A, *B;
    int mode;
    void* out;
    const float *bias, *res;
};

__global__ __launch_bounds__(256, 1) void tailg_k(TGp tg)
{
    extern __shared__ __align__(128) char smx[];
    const int tid = threadIdx.x, lane = tid & 31, wid = tid >> 5;
    const int wm = (wid & 3) * 32, wn = (wid >> 2) * 64;
    uint32_t sb = smem_u32(smx);

    int h = 0, row0, col0;
    if (tg.mode == 2) {
        h = blockIdx.x >> 2;
        row0 = (blockIdx.x & 3) * 128;
        col0 = 0;
    } else {
        row0 = (blockIdx.x / 7) * 128;
        col0 = (blockIdx.x % 7) * 128;
    }
    const int brow0 = (tg.mode == 2) ? (h * 112) : col0;

    float acc[2][8][4];
    #pragma unroll
    for (int mi = 0; mi < 2; mi++)
        #pragma unroll
        for (int nj = 0; nj < 8; nj++)
            #pragma unroll
            for (int q = 0; q < 4; q++) acc[mi][nj][q] = 0.0f;

    const int a_r = lane & 15;
    const int a_k = (lane >> 4) * 16;
    const int b_r = (lane & 7) + ((lane >> 4) & 1) * 8;
    const int b_k = ((lane >> 3) & 1) * 16;

    auto loadst = [&](uint32_t s0, int kt) {
        #pragma unroll
        for (int i = 0; i < 16; i++) {
            const int sel = i >> 3;
            int cc = (i & 7) * 256 + tid;
            int r = cc >> 4, ks = cc & 15;
            uint32_t dst = s0 + (uint32_t)sel * 34816u + (uint32_t)(r * TLDAB + ks * 16);
            if (sel == 0) {
                int rr = row0 + r;
                int grow = (tg.mode == 2) ? (((rr >> 3) << 6) + h * 8 + (rr & 7)) : rr;
                CP_ASYNC16(dst, tg.A + (size_t)grow * 896 + kt + ks * 8);
            } else {
                int brow = brow0 + r;
                if (brow > 895) brow = 895;
                CP_ASYNC16(dst, tg.B + (size_t)brow * 896 + kt + ks * 8);
            }
        }
        CP_COMMIT();
    };

    loadst(sb, 0);

    #pragma unroll 1
    for (int t = 0; t < 7; t++) {
        CP_WAIT0();
        __syncthreads();
        if (t + 1 < 7)
            loadst(sb + ((t + 1) & 1) * TSTAGE, (t + 1) * 128);

        uint32_t s0 = sb + (t & 1) * TSTAGE;
        uint32_t aB = s0 +          (uint32_t)((wm + a_r) * TLDAB + a_k);
        uint32_t bB = s0 + 34816u + (uint32_t)((wn + b_r) * TLDAB + b_k);
        #pragma unroll
        for (int ks = 0; ks < 8; ks++) {
            const uint32_t ksb = ks * 32;
            uint32_t a[2][4], bh[8][2];
            #pragma unroll
            for (int mi = 0; mi < 2; mi++)
                LDSM4(a[mi][0], a[mi][1], a[mi][2], a[mi][3], aB + mi * (16 * TLDAB) + ksb);
            #pragma unroll
            for (int p = 0; p < 4; p++)
                LDSM4(bh[2*p][0], bh[2*p][1], bh[2*p+1][0], bh[2*p+1][1], bB + p * (16 * TLDAB) + ksb);
            #pragma unroll
            for (int mi = 0; mi < 2; mi++)
                #pragma unroll
                for (int nj = 0; nj < 8; nj++)
                    MMA_F16(acc[mi][nj], a[mi], bh[nj][0], bh[nj][1]);
        }
        __syncthreads();
    }

    // ---------------- epilogue ----------------
    #pragma unroll
    for (int mi = 0; mi < 2; mi++) {
        #pragma unroll
        for (int half = 0; half < 2; half++) {
            int row = row0 + wm + mi * 16 + (lane >> 2) + half * 8;
            if (tg.mode == 2) {
                int bq = row >> 3, tq = row & 7;
                float stv = g_st[(bq * 8 + h) * 8 + tq];
                const float* op = g_oPart + ((size_t)(bq * 8 + h) * 8 + tq) * 112;
                __half* crow = g_ath + ((size_t)(bq * 8 + tq)) * 896 + h * 112;
                #pragma unroll
                for (int nj = 0; nj < 8; nj++) {
                    int gc = wn + nj * 8 + (lane & 3) * 2;
                    if (gc >= 112) continue;
                    float v0 = acc[mi][nj][half * 2]     + op[gc]     + stv * tg.bias[h * 112 + gc];
                    float v1 = acc[mi][nj][half * 2 + 1] + op[gc + 1] + stv * tg.bias[h * 112 + gc + 1];
                    __half2 h2 = __floats2half2_rn(v0, v1);
                    *(uint32_t*)(crow + gc) = *(uint32_t*)&h2;
                }
            } else {
                float* crow = (float*)tg.out + (size_t)row * DIMN;
                const float* rrow = (tg.mode == 0) ? (tg.res + (size_t)row * DIMN) : nullptr;
                #pragma unroll
                for (int nj = 0; nj < 8; nj++) {
                    int gc = col0 + wn + nj * 8 + (lane & 3) * 2;
                    float v0 = acc[mi][nj][half * 2]     + tg.bias[gc];
                    float v1 = acc[mi][nj][half * 2 + 1] + tg.bias[gc + 1];
                    float2 o;
                    if (tg.mode == 0) { o.x = v0 + rrow[gc]; o.y = v1 + rrow[gc + 1]; }
                    else              { o.x = fmaxf(v0, 0.f); o.y = fmaxf(v1, 0.f); }
                    *(float2*)(crow + gc) = o;
                }
            }
        }
    }
}

// ==================== attention (2-key score pass) ==========================
__global__ __launch_bounds__(256) void attn_k(const float* __restrict__ gate)
{
    const int b = blockIdx.x >> 3, h = blockIdx.x & 7;
    __shared__ float q_s[8][112];
    __shared__ float w_s[8][592];
    __shared__ const __half* kp[NKEYS];
    __shared__ const __half* vp[73];
    const int tid = threadIdx.x;

    for (int i = tid; i < 8 * 112; i += 256) {
        int r = i / 112, d = i % 112;
        q_s[r][d] = g_Q[((size_t)(b * 8 + r)) * 896 + h * 112 + d];
    }
    for (int k = tid; k < NKEYS; k += 256) {
        size_t o;
        if (k < 8)       { o = ((size_t)(b * 8 + k)) * 896 + h * 112;          kp[k] = g_Ks + o; vp[k] = g_Vs + o; }
        else if (k < 73) { o = ((size_t)(b * 65 + (k - 8))) * 896 + h * 112;   kp[k] = g_Ka + o; vp[k] = g_Va + o; }
        else             { o = ((size_t)(b * 512 + (k - 73))) * 896 + h * 112; kp[k] = g_Kt + o; }
    }
    __syncthreads();

    const float ratio = tanhf(gate[0]);
    const float sc0   = rsqrtf(112.0f);
    const float scT   = sc0 * ratio;

    // ---- scores: keys tid and tid+256 jointly (q LDS shared) ----
    {
        const __half* kbA = kp[tid];
        const __half* kbB = kp[tid + 256];
        float accA[8] = {0.f, 0.f, 0.f, 0.f, 0.f, 0.f, 0.f, 0.f};
        float accB[8] = {0.f, 0.f, 0.f, 0.f, 0.f, 0.f, 0.f, 0.f};
        #pragma unroll 2
        for (int d8 = 0; d8 < 14; ++d8) {
            uint4 rawA = *(const uint4*)(kbA + d8 * 8);
            uint4 rawB = *(const uint4*)(kbB + d8 * 8);
            const __half2* hA = (const __half2*)&rawA;
            const __half2* hB = (const __half2*)&rawB;
            float fA[8], fB[8];
            #pragma unroll
            for (int j = 0; j < 4; j++) {
                float2 a2 = __half22float2(hA[j]); fA[2*j] = a2.x; fA[2*j+1] = a2.y;
                float2 b2 = __half22float2(hB[j]); fB[2*j] = b2.x; fB[2*j+1] = b2.y;
            }
            #pragma unroll
            for (int r = 0; r < 8; r++) {
                const float* q = &q_s[r][d8 * 8];
                #pragma unroll
                for (int j = 0; j < 8; j++) {
                    accA[r] = fmaf(q[j], fA[j], accA[r]);
                    accB[r] = fmaf(q[j], fB[j], accB[r]);
                }
            }
        }
        float scA = (tid < 73) ? sc0 : scT;
        #pragma unroll
        for (int r = 0; r < 8; r++) {
            w_s[r][tid]       = accA[r] * scA;
            w_s[r][tid + 256] = accB[r] * scT;
        }
    }
    // ---- tail keys 512..584 ----
    if (tid < 73) {
        const __half* kb = kp[512 + tid];
        float acc[8] = {0.f, 0.f, 0.f, 0.f, 0.f, 0.f, 0.f, 0.f};
        #pragma unroll 2
        for (int d8 = 0; d8 < 14; ++d8) {
            uint4 raw = *(const uint4*)(kb + d8 * 8);
            const __half2* hp = (const __half2*)&raw;
            float f[8];
            #pragma unroll
            for (int j = 0; j < 4; j++) {
                float2 a2 = __half22float2(hp[j]); f[2*j] = a2.x; f[2*j+1] = a2.y;
            }
            #pragma unroll
            for (int r = 0; r < 8; r++) {
                const float* q = &q_s[r][d8 * 8];
                #pragma unroll
                for (int j = 0; j < 8; j++)
                    acc[r] = fmaf(q[j], f[j], acc[r]);
            }
        }
        #pragma unroll
        for (int r = 0; r < 8; r++) w_s[r][512 + tid] = acc[r] * scT;
    }
    __syncthreads();

    // ---- softmax (one warp per query row) + task weight-sum ----
    {
        int r = tid >> 5, lane = tid & 31;
        float m = -3.0e38f;
        for (int k = lane; k < NKEYS; k += 32) m = fmaxf(m, w_s[r][k]);
        #pragma unroll
        for (int o = 16; o; o >>= 1) m = fmaxf(m, __shfl_xor_sync(0xffffffffu, m, o));
        float s = 0.0f;
        for (int k = lane; k < NKEYS; k += 32) { float e = __expf(w_s[r][k] - m); w_s[r][k] = e; s += e; }
        #pragma unroll
        for (int o = 16; o; o >>= 1) s += __shfl_xor_sync(0xffffffffu, s, o);
        float inv = 1.0f / s;
        for (int k = lane; k < NKEYS; k += 32) w_s[r][k] *= inv;
        float sv = 0.0f;
        for (int k = 73 + lane; k < NKEYS; k += 32) sv += w_s[r][k];
        #pragma unroll
        for (int o = 16; o; o >>= 1) sv += __shfl_xor_sync(0xffffffffu, sv, o);
        if (lane == 0) g_st[(b * 8 + h) * 8 + r] = sv;
    }
    __syncthreads();

    for (int i = tid; i < 8 * 512; i += 256) {
        int t = i >> 9, k = i & 511;
        g_wt[((size_t)b * 64 + h * 8 + t) * 512 + k] = __float2half_rn(w_s[t][73 + k]);
    }

    for (int idx = tid; idx < 896; idx += 256) {
        int r = idx / 112, d = idx % 112;
        float acc = 0.0f;
        #pragma unroll 4
        for (int k = 0; k < 73; k++) acc = fmaf(w_s[r][k], __half2float(vp[k][d]), acc);
        g_oPart[((size_t)(b * 8 + h) * 8 + r) * 112 + d] = acc;
    }
}

// ==================== wsum GEMM: w_t[b](64x512) @ h_t[b](512x896), KB=64 ====
#define WS_LDA 72
#define WS_LDB 136
__global__ __launch_bounds__(256, 2) void wsum_k()
{
    __shared__ __half sA[2][64 * WS_LDA];
    __shared__ __half sB[2][64 * WS_LDB];
    const int bb = blockIdx.x / 7;
    const int col0 = (blockIdx.x % 7) * 128;
    const int tid = threadIdx.x, lane = tid & 31, wid = tid >> 5;
    const int wmi = wid >> 2, wni = wid & 3;

    const __half* Aw = g_wt  + (size_t)bb * 64 * 512;
    const __half* Bh = g_hth + (size_t)bb * 512 * 896 + col0;

    float acc[2][4][4];
    #pragma unroll
    for (int mi = 0; mi < 2; mi++)
        #pragma unroll
        for (int nj = 0; nj < 4; nj++)
            #pragma unroll
            for (int q = 0; q < 4; q++) acc[mi][nj][q] = 0.0f;

    const int bt_k = (lane % 8) + (lane & 8);
    const int bt_n = (lane & 16) >> 1;

    auto loadst = [&](int st, int kt) {
        #pragma unroll
        for (int i = 0; i < 2; i++) {
            int idx = i * 256 + tid;
            int r = idx >> 3, c = idx & 7;
            CP_ASYNC16(smem_u32(&sA[st][r * WS_LDA + c * 8]), Aw + (size_t)r * 512 + kt + c * 8);
        }
        #pragma unroll
        for (int i = 0; i < 4; i++) {
            int idx = i * 256 + tid;
            int rr = idx >> 4, cx = idx & 15;
            CP_ASYNC16(smem_u32(&sB[st][rr * WS_LDB + cx * 8]), Bh + (size_t)(kt + rr) * 896 + cx * 8);
        }
        CP_COMMIT();
    };

    loadst(0, 0);

    #pragma unroll 1
    for (int t = 0; t < 8; t++) {
        CP_WAIT0();
        __syncthreads();
        if (t + 1 < 8)
            loadst((t + 1) & 1, (t + 1) * 64);
        const int buf = t & 1;
        #pragma unroll
        for (int ks = 0; ks < 4; ks++) {
            uint32_t a[2][4], bf[4][2];
            #pragma unroll
            for (int mi = 0; mi < 2; mi++) {
                uint32_t aaddr = smem_u32(&sA[buf][(wmi * 32 + mi * 16 + (lane & 15)) * WS_LDA])
                                 + ((lane >> 4) * 16) + ks * 32;
                LDSM4(a[mi][0], a[mi][1], a[mi][2], a[mi][3], aaddr);
            }
            #pragma unroll
            for (int nb = 0; nb < 2; nb++) {
                uint32_t baddr = smem_u32(&sB[buf][(ks * 16 + bt_k) * WS_LDB
                                  + wni * 32 + nb * 16 + bt_n]);
                LDSM4_T(bf[2*nb][0], bf[2*nb][1], bf[2*nb+1][0], bf[2*nb+1][1], baddr);
            }
            #pragma unroll
            for (int mi = 0; mi < 2; mi++)
                #pragma unroll
                for (int nj = 0; nj < 4; nj++)
                    MMA_F16(acc[mi][nj], a[mi], bf[nj][0], bf[nj][1]);
        }
        __syncthreads();
    }

    #pragma unroll
    for (int mi = 0; mi < 2; mi++) {
        #pragma unroll
        for (int half = 0; half < 2; half++) {
            int r = wmi * 32 + mi * 16 + (lane >> 2) + half * 8;
            __half* crow = g_wsum + ((size_t)bb * 64 + r) * 896;
            #pragma unroll
            for (int nj = 0; nj < 4; nj++) {
                int gc = col0 + wni * 32 + nj * 8 + (lane & 3) * 2;
                __half2 h2 = __floats2half2_rn(acc[mi][nj][half * 2], acc[mi][nj][half * 2 + 1]);
                *(uint32_t*)(crow + gc) = *(uint32_t*)&h2;
            }
        }
    }
}

// ==================== layernorm (emits fp16) ================================
__global__ __launch_bounds__(256) void ln_k(const float* __restrict__ g,
                                            const float* __restrict__ bt)
{
    int row = blockIdx.x;
    const float* y = g_y + (size_t)row * 896;
    int tid = threadIdx.x;
    float s = 0.0f, s2 = 0.0f;
    for (int j = tid; j < 896; j += 256) { float v = y[j]; s += v; s2 += v * v; }
    __shared__ float rs[8], rs2[8];
    #pragma unroll
    for (int o = 16; o; o >>= 1) { s += __shfl_xor_sync(~0u, s, o); s2 += __shfl_xor_sync(~0u, s2, o); }
    if ((tid & 31) == 0) { rs[tid >> 5] = s; rs2[tid >> 5] = s2; }
    __syncthreads();
    if (tid < 32) {
        s  = (tid < 8) ? rs[tid]  : 0.0f;
        s2 = (tid < 8) ? rs2[tid] : 0.0f;
        #pragma unroll
        for (int o = 4; o; o >>= 1) { s += __shfl_xor_sync(~0u, s, o); s2 += __shfl_xor_sync(~0u, s2, o); }
        if (tid == 0) { rs[0] = s; rs2[0] = s2; }
    }
    __syncthreads();
    float mu  = rs[0]  * (1.0f / 896.0f);
    float var = rs2[0] * (1.0f / 896.0f) - mu * mu;
    float inv = rsqrtf(var + 1e-5f);
    for (int j = tid; j < 896; j += 256)
        g_ynh[(size_t)row * 896 + j] = __float2half_rn((y[j] - mu) * inv * g[j] + bt[j]);
}

// ==================== host orchestration ====================================
extern "C" void kernel_launch(void* const* d_in, const int* in_sizes, int n_in,
                              void* d_out, int out_size)
{
    const float* x   = (const float*)d_in[0];
    const float* h_a = (const float*)d_in[1];
    const float* h_t = (const float*)d_in[2];
    const float* p   = (const float*)d_in[3];
    const float* Wq  = (const float*)d_in[4],  *bq  = (const float*)d_in[5];
    const float* Wks = (const float*)d_in[6],  *bks = (const float*)d_in[7];
    const float* Wvs = (const float*)d_in[8],  *bvs = (const float*)d_in[9];
    const float* Wka = (const float*)d_in[10], *bka = (const float*)d_in[11];
    const float* Wva = (const float*)d_in[12], *bva = (const float*)d_in[13];
    const float* Wkt = (const float*)d_in[14], *bkt = (const float*)d_in[15];
    const float* Wvt = (const float*)d_in[16], *bvt = (const float*)d_in[17];
    const float* Wo  = (const float*)d_in[18], *bo  = (const float*)d_in[19];
    const float* Wf  = (const float*)d_in[20], *bf  = (const float*)d_in[21];
    const float* gate = (const float*)d_in[22];
    const float* ln_g = (const float*)d_in[23];
    const float* ln_b = (const float*)d_in[24];

    float *Q, *y;
    __half *Ks, *Vs, *Ka, *Va, *Kt;
    __half *W, *xh, *hadh, *hth, *ath, *ynh, *wsum;
    cudaGetSymbolAddress((void**)&Q,    g_Q);
    cudaGetSymbolAddress((void**)&Ks,   g_Ks);
    cudaGetSymbolAddress((void**)&Vs,   g_Vs);
    cudaGetSymbolAddress((void**)&Ka,   g_Ka);
    cudaGetSymbolAddress((void**)&Va,   g_Va);
    cudaGetSymbolAddress((void**)&Kt,   g_Kt);
    cudaGetSymbolAddress((void**)&y,    g_y);
    cudaGetSymbolAddress((void**)&W,    g_W);
    cudaGetSymbolAddress((void**)&xh,   g_xh);
    cudaGetSymbolAddress((void**)&hadh, g_hadh);
    cudaGetSymbolAddress((void**)&hth,  g_hth);
    cudaGetSymbolAddress((void**)&ath,  g_ath);
    cudaGetSymbolAddress((void**)&ynh,  g_ynh);
    cudaGetSymbolAddress((void**)&wsum, g_wsum);

    cudaFuncSetAttribute(wgemm_k, cudaFuncAttributeMaxDynamicSharedMemorySize, SM_TOTAL);
    cudaFuncSetAttribute(tailg_k, cudaFuncAttributeMaxDynamicSharedMemorySize, TSM);

    cvt_k<<<(32768 * 224 + 255) / 256, 256>>>(h_t, hth, 32768 * 224);

    {
        PrepArgs pa;
        pa.w[0] = Wq; pa.w[1] = Wks; pa.w[2] = Wvs; pa.w[3] = Wka; pa.w[4] = Wva;
        pa.w[5] = Wkt; pa.w[6] = Wvt; pa.w[7] = Wo; pa.w[8] = Wf;
        pa.x = x; pa.h_a = h_a; pa.p = p;
        prep2_k<<<SEG_ROPE, 256>>>(pa);
    }

    const size_t WS = 896 * 896;

    // ---- batched GEMM: Kt (1792) + Ka/Va (462) + QKV (84) ------------------
    {
        GB3 gb;
        gb.g[0].Ah = hth; gb.g[0].B = W + 5 * WS;
        gb.g[0].M = 32768; gb.g[0].ncol = 7;
        gb.g[0].out[0] = Kt; gb.g[0].bias[0] = bkt; gb.g[0].epi[0] = 1; gb.g[0].rl[0] = 512; gb.g[0].hout[0] = 1;
        gb.g[0].out[1] = nullptr; gb.g[0].bias[1] = nullptr; gb.g[0].epi[1] = 0; gb.g[0].rl[1] = 1; gb.g[0].hout[1] = 0;
        gb.g[0].out[2] = nullptr; gb.g[0].bias[2] = nullptr; gb.g[0].epi[2] = 0; gb.g[0].rl[2] = 1; gb.g[0].hout[2] = 0;
        gb.g[0].res = nullptr;

        gb.g[1].Ah = hadh; gb.g[1].B = W + 3 * WS;
        gb.g[1].M = 4160; gb.g[1].ncol = 14;
        gb.g[1].out[0] = Ka; gb.g[1].bias[0] = bka; gb.g[1].epi[0] = 1; gb.g[1].rl[0] = 65; gb.g[1].hout[0] = 1;
        gb.g[1].out[1] = Va; gb.g[1].bias[1] = bva; gb.g[1].epi[1] = 0; gb.g[1].rl[1] = 1;  gb.g[1].hout[1] = 1;
        gb.g[1].out[2] = nullptr; gb.g[1].bias[2] = nullptr; gb.g[1].epi[2] = 0; gb.g[1].rl[2] = 1; gb.g[1].hout[2] = 0;
        gb.g[1].res = nullptr;

        gb.g[2].Ah = xh; gb.g[2].B = W;
        gb.g[2].M = 512; gb.g[2].ncol = 21;
        gb.g[2].out[0] = Q;  gb.g[2].bias[0] = bq;  gb.g[2].epi[0] = 1; gb.g[2].rl[0] = 8; gb.g[2].hout[0] = 0;
        gb.g[2].out[1] = Ks; gb.g[2].bias[1] = bks; gb.g[2].epi[1] = 1; gb.g[2].rl[1] = 8; gb.g[2].hout[1] = 1;
        gb.g[2].out[2] = Vs; gb.g[2].bias[2] = bvs; gb.g[2].epi[2] = 0; gb.g[2].rl[2] = 1; gb.g[2].hout[2] = 1;
        gb.g[2].res = nullptr;
        gb.b0 = 1792; gb.b1 = 1792 + 462;
        wgemm_k<<<1792 + 462 + 84, 256, SM_TOTAL>>>(gb);
    }

    attn_k<<<512, 256>>>(gate);
    wsum_k<<<64 * 7, 256>>>();

    // ---- proj (mode 2): 32 CTAs, KB=128 -------------------------------------
    {
        TGp tg;
        tg.A = wsum; tg.B = W + 6 * WS; tg.mode = 2;
        tg.out = nullptr; tg.bias = bvt; tg.res = nullptr;
        tailg_k<<<32, 256, TSM>>>(tg);
    }

    // ---- Wo (mode 0): 28 CTAs, KB=128 ---------------------------------------
    {
        TGp tg;
        tg.A = ath; tg.B = W + 7 * WS; tg.mode = 0;
        tg.out = y; tg.bias = bo; tg.res = x;
        tailg_k<<<28, 256, TSM>>>(tg);
    }

    ln_k<<<512, 256>>>(ln_g, ln_b);

    // ---- Wf (mode 1): 28 CTAs, KB=128 ---------------------------------------
    {
        TGp tg;
        tg.A = ynh; tg.B = W + 8 * WS; tg.mode = 1;
        tg.out = d_out; tg.bias = bf; tg.res = nullptr;
        tailg_k<<<28, 256, TSM>>>(tg);
    }
}